// round 4
// baseline (speedup 1.0000x reference)
#include <cuda_runtime.h>
#include <cstdint>

// ---------------------------------------------------------------------------
// RelationalKENN: unary clause enhancement + binary (edge) clause enhancement
//   up = (unary + d_unary) scatter-added with edge deltas at index1/index2
//   bp = binary + d_binary
// Output layout: [ up : n_nodes*16 floats ][ bp : n_edges*4 floats ]
// ---------------------------------------------------------------------------

#define MAX_NODES 100096  // problem fixes n_nodes = 100000
#define CHUNK     256     // edges per work item (1 per thread)
#define NBLOCKS   912     // 152 SMs * 6 resident blocks
#define NTHREADS  256

// Pre-scatter u columns 0..3 per node (only cols 0..3 feed the binary clauses).
__device__ float4 g_u03[MAX_NODES];
// Dynamic work-stealing ticket for the edge kernel.
__device__ int g_ticket;

__global__ void __launch_bounds__(256)
unary_enhance_kernel(const float* __restrict__ unary,
                     const float* __restrict__ w,
                     float*       __restrict__ up,       // d_out up region
                     int n_nodes)
{
    // Reset the edge-kernel ticket (kernel boundary orders this before use).
    if (blockIdx.x == 0 && threadIdx.x == 0) g_ticket = 0;

    int row = blockIdx.x * blockDim.x + threadIdx.x;
    if (row >= n_nodes) return;

    const float4* in4 = reinterpret_cast<const float4*>(unary) + (size_t)row * 4;
    float4 a = in4[0], b = in4[1], c = in4[2], d = in4[3];
    float x[16] = { a.x, a.y, a.z, a.w,  b.x, b.y, b.z, b.w,
                    c.x, c.y, c.z, c.w,  d.x, d.y, d.z, d.w };
    float dlt[16];
#pragma unroll
    for (int i = 0; i < 16; i++) dlt[i] = 0.0f;

    auto clause2 = [&](int i, int j, float wt) {
        float ea = __expf(-x[i]);
        float eb = __expf( x[j]);
        float r  = __fdividef(wt, ea + eb);
        dlt[i] -= ea * r;
        dlt[j] += eb * r;
    };
    auto clause3 = [&](int i, int j, int k, float wt) {
        float ea = __expf(-x[i]);
        float eb = __expf( x[j]);
        float ec = __expf( x[k]);
        float r  = __fdividef(wt, ea + eb + ec);
        dlt[i] -= ea * r;
        dlt[j] += eb * r;
        dlt[k] += ec * r;
    };

    clause2(0, 1,       w[0]);
    clause2(1, 2,       w[1]);
    clause3(2, 3, 4,    w[2]);
    clause2(4, 5,       w[3]);
    clause3(6, 7, 8,    w[4]);
    clause2(8, 9,       w[5]);
    clause3(10, 11, 12, w[6]);
    clause3(13, 14, 15, w[7]);

    float u[16];
#pragma unroll
    for (int i = 0; i < 16; i++) u[i] = x[i] + dlt[i];

    float4* o4 = reinterpret_cast<float4*>(up) + (size_t)row * 4;
    o4[0] = make_float4(u[0],  u[1],  u[2],  u[3]);
    o4[1] = make_float4(u[4],  u[5],  u[6],  u[7]);
    o4[2] = make_float4(u[8],  u[9],  u[10], u[11]);
    o4[3] = make_float4(u[12], u[13], u[14], u[15]);

    g_u03[row] = make_float4(u[0], u[1], u[2], u[3]);
}

// Per-edge math + stores, given preloaded operands.
__device__ __forceinline__ void edge_compute(float4 v1, float4 v2, float4 bv,
                                             float w0, float w1, float w2, float w3,
                                             float* __restrict__ up,
                                             float4* __restrict__ bp_e,
                                             int i1, int i2)
{
    float U1[4] = { v1.x, v1.y, v1.z, v1.w };
    float U2[4] = { v2.x, v2.y, v2.z, v2.w };
    float B [4] = { bv.x, bv.y, bv.z, bv.w };
    float W [4] = { w0, w1, w2, w3 };

    float du1[4], du2[4], bo[4];
#pragma unroll
    for (int k = 0; k < 4; k++) {
        // clause k: literals (u1[k]:-1, binary[k]:-1, u2[k]:+1)
        float ea = __expf(-U1[k]);
        float eb = __expf(-B[k]);
        float ec = __expf( U2[k]);
        float r  = __fdividef(W[k], ea + eb + ec);
        du1[k] = -ea * r;
        bo[k]  =  B[k] - eb * r;
        du2[k] =  ec * r;
    }

    *bp_e = make_float4(bo[0], bo[1], bo[2], bo[3]);

    float* p1 = up + (size_t)i1 * 16;
    float* p2 = up + (size_t)i2 * 16;
    asm volatile("red.global.add.v4.f32 [%0], {%1, %2, %3, %4};"
                 :: "l"(p1), "f"(du1[0]), "f"(du1[1]), "f"(du1[2]), "f"(du1[3])
                 : "memory");
    asm volatile("red.global.add.v4.f32 [%0], {%1, %2, %3, %4};"
                 :: "l"(p2), "f"(du2[0]), "f"(du2[1]), "f"(du2[2]), "f"(du2[3])
                 : "memory");
}

// Persistent blocks; each grabs 256-edge chunks via an atomic ticket.
// Every access stays perfectly warp-coalesced (one edge per thread).
__global__ void __launch_bounds__(NTHREADS, 6)
binary_enhance_kernel(const float* __restrict__ binary,
                      const int*   __restrict__ index1,
                      const int*   __restrict__ index2,
                      const float* __restrict__ w,
                      float*       __restrict__ up,      // atomic target
                      float*       __restrict__ bp,      // d_out bp region
                      int n_edges)
{
    __shared__ int s_chunk;

    float w0 = __ldg(w+0), w1 = __ldg(w+1), w2 = __ldg(w+2), w3 = __ldg(w+3);

    const float4* b4  = reinterpret_cast<const float4*>(binary);
    float4*       bp4 = reinterpret_cast<float4*>(bp);

    int n_chunks = (n_edges + CHUNK - 1) / CHUNK;

    for (;;) {
        if (threadIdx.x == 0)
            s_chunk = atomicAdd(&g_ticket, 1);
        __syncthreads();
        int chunk = s_chunk;
        __syncthreads();                 // protect s_chunk before next overwrite
        if (chunk >= n_chunks) return;

        int e = chunk * CHUNK + threadIdx.x;
        if (e >= n_edges) continue;      // only possible in the last chunk

        int i1 = index1[e];
        int i2 = index2[e];
        float4 v1 = g_u03[i1];
        float4 v2 = g_u03[i2];
        float4 bv = b4[e];

        edge_compute(v1, v2, bv, w0, w1, w2, w3, up, bp4 + e, i1, i2);
    }
}

extern "C" void kernel_launch(void* const* d_in, const int* in_sizes, int n_in,
                              void* d_out, int out_size)
{
    const float* unary   = (const float*)d_in[0];
    const float* binary  = (const float*)d_in[1];
    const int*   index1  = (const int*)  d_in[2];
    const int*   index2  = (const int*)  d_in[3];
    const float* uw      = (const float*)d_in[4];
    const float* bw      = (const float*)d_in[5];

    int n_nodes = in_sizes[0] / 16;
    int n_edges = in_sizes[2];

    float* up = (float*)d_out;
    float* bp = up + (size_t)n_nodes * 16;

    unary_enhance_kernel<<<(n_nodes + 255) / 256, 256>>>(unary, uw, up, n_nodes);

    int n_chunks = (n_edges + CHUNK - 1) / CHUNK;
    int blocks = NBLOCKS < n_chunks ? NBLOCKS : n_chunks;
    binary_enhance_kernel<<<blocks, NTHREADS>>>(binary, index1, index2,
                                                bw, up, bp, n_edges);
}

// round 7
// speedup vs baseline: 1.0387x; 1.0387x over previous
#include <cuda_runtime.h>
#include <cstdint>

// ---------------------------------------------------------------------------
// RelationalKENN: unary clause enhancement + binary (edge) clause enhancement
//   up = (unary + d_unary) scatter-added with edge deltas at index1/index2
//   bp = binary + d_binary
// Output layout: [ up : n_nodes*16 floats ][ bp : n_edges*4 floats ]
//
// v6: binary kernel = proven-fastest R1 shape (1 edge/thread, fully coalesced
// streams, 2x red.global.add.v4). New: programmatic dependent launch overlaps
// the binary kernel's unary-independent stream loads + launch gap with the
// tail of the unary kernel. Falls back to a plain serialized launch if the
// PDL launch attribute is unavailable.
// ---------------------------------------------------------------------------

#define MAX_NODES 100096  // problem fixes n_nodes = 100000

// Pre-scatter u columns 0..3 per node (only cols 0..3 feed the binary clauses).
__device__ __align__(16) float4 g_u03[MAX_NODES];

__global__ void __launch_bounds__(256)
unary_enhance_kernel(const float* __restrict__ unary,
                     const float* __restrict__ w,
                     float*       __restrict__ up,       // d_out up region
                     int n_nodes)
{
    int row = blockIdx.x * blockDim.x + threadIdx.x;
    if (row < n_nodes) {
        const float4* in4 = reinterpret_cast<const float4*>(unary) + (size_t)row * 4;
        float4 a = in4[0], b = in4[1], c = in4[2], d = in4[3];
        float x[16] = { a.x, a.y, a.z, a.w,  b.x, b.y, b.z, b.w,
                        c.x, c.y, c.z, c.w,  d.x, d.y, d.z, d.w };
        float dlt[16];
#pragma unroll
        for (int i = 0; i < 16; i++) dlt[i] = 0.0f;

        auto clause2 = [&](int i, int j, float wt) {
            float ea = __expf(-x[i]);
            float eb = __expf( x[j]);
            float r  = __fdividef(wt, ea + eb);
            dlt[i] -= ea * r;
            dlt[j] += eb * r;
        };
        auto clause3 = [&](int i, int j, int k, float wt) {
            float ea = __expf(-x[i]);
            float eb = __expf( x[j]);
            float ec = __expf( x[k]);
            float r  = __fdividef(wt, ea + eb + ec);
            dlt[i] -= ea * r;
            dlt[j] += eb * r;
            dlt[k] += ec * r;
        };

        clause2(0, 1,       w[0]);
        clause2(1, 2,       w[1]);
        clause3(2, 3, 4,    w[2]);
        clause2(4, 5,       w[3]);
        clause3(6, 7, 8,    w[4]);
        clause2(8, 9,       w[5]);
        clause3(10, 11, 12, w[6]);
        clause3(13, 14, 15, w[7]);

        float u[16];
#pragma unroll
        for (int i = 0; i < 16; i++) u[i] = x[i] + dlt[i];

        float4* o4 = reinterpret_cast<float4*>(up) + (size_t)row * 4;
        o4[0] = make_float4(u[0],  u[1],  u[2],  u[3]);
        o4[1] = make_float4(u[4],  u[5],  u[6],  u[7]);
        o4[2] = make_float4(u[8],  u[9],  u[10], u[11]);
        o4[3] = make_float4(u[12], u[13], u[14], u[15]);

        g_u03[row] = make_float4(u[0], u[1], u[2], u[3]);
    }

#if __CUDA_ARCH__ >= 900
    // Allow the dependent binary kernel to start its pre-sync phase.
    cudaTriggerProgrammaticLaunchCompletion();
#endif
}

__global__ void __launch_bounds__(256)
binary_enhance_kernel(const float* __restrict__ binary,
                      const int*   __restrict__ index1,
                      const int*   __restrict__ index2,
                      const float* __restrict__ w,
                      float*       __restrict__ up,      // atomic target
                      float*       __restrict__ bp,      // d_out bp region
                      int n_edges)
{
    int e = blockIdx.x * blockDim.x + threadIdx.x;
    bool valid = e < n_edges;

    // ---- pre-sync phase: everything independent of the unary kernel ----
    int i1 = 0, i2 = 0;
    float4 bv = make_float4(0.f, 0.f, 0.f, 0.f);
    if (valid) {
        i1 = index1[e];
        i2 = index2[e];
        bv = reinterpret_cast<const float4*>(binary)[e];
    }
    float w0 = __ldg(w+0), w1 = __ldg(w+1), w2 = __ldg(w+2), w3 = __ldg(w+3);

#if __CUDA_ARCH__ >= 900
    // Wait until the unary kernel's writes (g_u03, up) are visible.
    cudaGridDependencySynchronize();
#endif

    if (!valid) return;

    // ---- post-sync phase: gathers + math + scatter ----
    float4 v1 = g_u03[i1];
    float4 v2 = g_u03[i2];

    float U1[4] = { v1.x, v1.y, v1.z, v1.w };
    float U2[4] = { v2.x, v2.y, v2.z, v2.w };
    float B [4] = { bv.x, bv.y, bv.z, bv.w };
    float W [4] = { w0, w1, w2, w3 };

    float du1[4], du2[4], bo[4];
#pragma unroll
    for (int k = 0; k < 4; k++) {
        // clause k: literals (u1[k]:-1, binary[k]:-1, u2[k]:+1)
        float ea = __expf(-U1[k]);
        float eb = __expf(-B[k]);
        float ec = __expf( U2[k]);
        float r  = __fdividef(W[k], ea + eb + ec);
        du1[k] = -ea * r;
        bo[k]  =  B[k] - eb * r;
        du2[k] =  ec * r;
    }

    reinterpret_cast<float4*>(bp)[e] = make_float4(bo[0], bo[1], bo[2], bo[3]);

    float* p1 = up + (size_t)i1 * 16;
    float* p2 = up + (size_t)i2 * 16;
    asm volatile("red.global.add.v4.f32 [%0], {%1, %2, %3, %4};"
                 :: "l"(p1), "f"(du1[0]), "f"(du1[1]), "f"(du1[2]), "f"(du1[3])
                 : "memory");
    asm volatile("red.global.add.v4.f32 [%0], {%1, %2, %3, %4};"
                 :: "l"(p2), "f"(du2[0]), "f"(du2[1]), "f"(du2[2]), "f"(du2[3])
                 : "memory");
}

extern "C" void kernel_launch(void* const* d_in, const int* in_sizes, int n_in,
                              void* d_out, int out_size)
{
    const float* unary   = (const float*)d_in[0];
    const float* binary  = (const float*)d_in[1];
    const int*   index1  = (const int*)  d_in[2];
    const int*   index2  = (const int*)  d_in[3];
    const float* uw      = (const float*)d_in[4];
    const float* bw      = (const float*)d_in[5];

    int n_nodes = in_sizes[0] / 16;
    int n_edges = in_sizes[2];

    float* up = (float*)d_out;
    float* bp = up + (size_t)n_nodes * 16;

    unary_enhance_kernel<<<(n_nodes + 255) / 256, 256>>>(unary, uw, up, n_nodes);

    int n_blocks = (n_edges + 255) / 256;

    // Programmatic dependent launch: let the binary kernel's pre-sync phase
    // (stream loads of index/binary) overlap the unary kernel's tail.
    cudaLaunchConfig_t cfg = {};
    cfg.gridDim  = dim3((unsigned)n_blocks, 1, 1);
    cfg.blockDim = dim3(256, 1, 1);
    cfg.dynamicSmemBytes = 0;
    cfg.stream = 0;  // same (legacy default) stream the <<<>>> launch used
    cudaLaunchAttribute attrs[1];
    attrs[0].id = cudaLaunchAttributeProgrammaticStreamSerialization;
    attrs[0].val.programmaticStreamSerializationAllowed = 1;
    cfg.attrs = attrs;
    cfg.numAttrs = 1;

    cudaError_t err = cudaLaunchKernelEx(&cfg, binary_enhance_kernel,
                                         binary, index1, index2, bw,
                                         up, bp, n_edges);
    if (err != cudaSuccess) {
        // Fallback: plain serialized launch (identical semantics).
        binary_enhance_kernel<<<n_blocks, 256>>>(binary, index1, index2, bw,
                                                 up, bp, n_edges);
    }
}